// round 2
// baseline (speedup 1.0000x reference)
#include <cuda_runtime.h>
#include <cuda_bf16.h>
#include <math.h>

// Problem constants
#define BB   256                 // batch
#define TT   2048                // seq len
#define VV   128                 // vocab / input size
#define HH   64                  // hidden
#define GG   256                 // 4 gates * HH
#define MM   (BB * TT)           // 524288 rows

// Scratch (device-global; no runtime allocation allowed)
__device__ float g_Wx[VV * GG];            // fused x-part weights [128,256]
__device__ float g_Wh[HH * GG];            // fused h-part weights [64,256]
__device__ float g_bias[GG];               // fused gate biases
__device__ float g_preact[(size_t)MM * GG];  // 512 MB: x-part preactivations
__device__ float g_H[(size_t)MM * HH];       // 128 MB: hidden states per step

// ---------------------------------------------------------------------------
// Kernel 0: pack 4 gate weight matrices into fused layouts.
// Gate order: 0..63 = f, 64..127 = if, 128..191 = ic(tanh), 192..255 = o
// ---------------------------------------------------------------------------
__global__ void pack_weights(const float* __restrict__ Wf,  const float* __restrict__ bf,
                             const float* __restrict__ Wif, const float* __restrict__ bif,
                             const float* __restrict__ Wic, const float* __restrict__ bic,
                             const float* __restrict__ Wo,  const float* __restrict__ bo) {
    int g = blockIdx.x * blockDim.x + threadIdx.x;
    if (g >= GG) return;
    int gate = g >> 6;
    int col  = g & 63;
    const float* W = (gate == 0) ? Wf : (gate == 1) ? Wif : (gate == 2) ? Wic : Wo;
    const float* bv = (gate == 0) ? bf : (gate == 1) ? bif : (gate == 2) ? bic : bo;
    g_bias[g] = bv[col];
    for (int k = 0; k < VV; k++)
        g_Wx[k * GG + g] = W[k * HH + col];
    for (int j = 0; j < HH; j++)
        g_Wh[j * GG + g] = W[(VV + j) * HH + col];
}

// ---------------------------------------------------------------------------
// Kernel 1: preact[m, g] = x[m, :] @ Wx[:, g] + bias[g]
// M=524288, N=256, K=128.  Tiles: BM=64, BN=64, BK=16; 256 threads, 4x4/thread.
// ---------------------------------------------------------------------------
__global__ __launch_bounds__(256) void gemm_x(const float* __restrict__ x) {
    __shared__ float As[16][68];   // [k][m], padded to reduce store conflicts
    __shared__ float Bs[16][64];   // [k][n]

    const int m0 = blockIdx.x * 64;
    const int n0 = blockIdx.y * 64;
    const int tid = threadIdx.x;
    const int tx = tid & 15;       // n-group
    const int ty = tid >> 4;       // m-group

    float acc[4][4] = {};

    for (int k0 = 0; k0 < VV; k0 += 16) {
        // Load A tile (64 rows x 16 k), transposed into As[k][m]
        {
            int r  = tid >> 2;
            int kq = (tid & 3) * 4;
            float4 v = *reinterpret_cast<const float4*>(&x[(size_t)(m0 + r) * VV + k0 + kq]);
            As[kq + 0][r] = v.x;
            As[kq + 1][r] = v.y;
            As[kq + 2][r] = v.z;
            As[kq + 3][r] = v.w;
        }
        // Load B tile (16 k x 64 n) via float4
        {
            int kk = tid >> 4;
            int c4 = (tid & 15) * 4;
            *reinterpret_cast<float4*>(&Bs[kk][c4]) =
                *reinterpret_cast<const float4*>(&g_Wx[(size_t)(k0 + kk) * GG + n0 + c4]);
        }
        __syncthreads();

        #pragma unroll
        for (int kk = 0; kk < 16; kk++) {
            float4 a = *reinterpret_cast<float4*>(&As[kk][ty * 4]);
            float4 b = *reinterpret_cast<float4*>(&Bs[kk][tx * 4]);
            float av[4] = {a.x, a.y, a.z, a.w};
            float bv[4] = {b.x, b.y, b.z, b.w};
            #pragma unroll
            for (int i = 0; i < 4; i++)
                #pragma unroll
                for (int j = 0; j < 4; j++)
                    acc[i][j] = fmaf(av[i], bv[j], acc[i][j]);
        }
        __syncthreads();
    }

    // Epilogue: add bias, store
    float4 bias4 = *reinterpret_cast<const float4*>(&g_bias[n0 + tx * 4]);
    #pragma unroll
    for (int i = 0; i < 4; i++) {
        float4 o;
        o.x = acc[i][0] + bias4.x;
        o.y = acc[i][1] + bias4.y;
        o.z = acc[i][2] + bias4.z;
        o.w = acc[i][3] + bias4.w;
        *reinterpret_cast<float4*>(
            &g_preact[(size_t)(m0 + ty * 4 + i) * GG + n0 + tx * 4]) = o;
    }
}

// ---------------------------------------------------------------------------
// Kernel 2: recurrent LSTM. One CTA per batch row, 256 threads (one per gate
// column). W_h lives in registers (64 floats/thread). h broadcast via SMEM,
// c held in registers of threads 0..63. Stores h_t to g_H each step.
// ---------------------------------------------------------------------------
__global__ __launch_bounds__(256, 2) void lstm_kernel() {
    const int b = blockIdx.x;
    const int g = threadIdx.x;

    __shared__ float h_s[HH];
    __shared__ float gates_s[GG];

    // Load this thread's W_h column into registers
    float wh[HH];
    #pragma unroll
    for (int j = 0; j < HH; j++)
        wh[j] = g_Wh[j * GG + g];

    float c = 0.f;
    if (g < HH) h_s[g] = 0.f;
    __syncthreads();

    const float* pa = g_preact + (size_t)b * TT * GG + g;
    float* hout = g_H + (size_t)b * TT * HH;

    float p = pa[0];

    for (int t = 0; t < TT; t++) {
        // Prefetch next step's preactivation (hidden behind the FMA loop)
        int tn = (t + 1 < TT) ? (t + 1) : t;
        float pnext = __ldg(&pa[(size_t)tn * GG]);

        // acc = preact + h @ Wh[:, g]
        float acc0 = p, acc1 = 0.f;
        #pragma unroll
        for (int j = 0; j < HH; j += 4) {
            float4 hv = *reinterpret_cast<float4*>(&h_s[j]);
            acc0 = fmaf(hv.x, wh[j + 0], acc0);
            acc1 = fmaf(hv.y, wh[j + 1], acc1);
            acc0 = fmaf(hv.z, wh[j + 2], acc0);
            acc1 = fmaf(hv.w, wh[j + 3], acc1);
        }
        float v = acc0 + acc1;

        // Gate nonlinearity: groups 0,1,3 sigmoid; group 2 tanh
        float val;
        if ((g >> 6) == 2) {
            val = tanhf(v);
        } else {
            val = 1.f / (1.f + expf(-v));
        }
        gates_s[g] = val;
        __syncthreads();

        if (g < HH) {
            float f   = gates_s[g];
            float af  = gates_s[HH + g];
            float add = gates_s[2 * HH + g];
            float o   = gates_s[3 * HH + g];
            c = fmaf(c, f, add * af);
            float hn = tanhf(c) * o;
            h_s[g] = hn;
            hout[(size_t)t * HH + g] = hn;
        }
        __syncthreads();

        p = pnext;
    }
}

// ---------------------------------------------------------------------------
// Kernel 3: out[m, :] = softmax(h[m, :] @ W_out + b_out)
// 256 threads/block = 8 warps; block tile = 32 rows; each warp 4 rows;
// each lane 4 output columns.  W_out (32 KB) + h tile (8 KB) in SMEM.
// ---------------------------------------------------------------------------
__global__ __launch_bounds__(256) void out_proj(const float* __restrict__ Wout,
                                                const float* __restrict__ bout,
                                                float* __restrict__ out) {
    __shared__ float Ws[HH][VV];       // 32 KB
    __shared__ float hs[32][HH];       // 8 KB
    __shared__ float bs[VV];

    const int r0  = blockIdx.x * 32;
    const int tid = threadIdx.x;

    // Load W_out (64x128 = 2048 float4s, 8 per thread)
    #pragma unroll
    for (int pss = 0; pss < 8; pss++) {
        int idx = pss * 256 + tid;          // float4 index 0..2047
        int rr = idx >> 5;
        int cc = (idx & 31) * 4;
        *reinterpret_cast<float4*>(&Ws[rr][cc]) =
            *reinterpret_cast<const float4*>(&Wout[rr * VV + cc]);
    }
    if (tid < VV) bs[tid] = bout[tid];

    // Load h tile (32 rows x 64 = 512 float4s, 2 per thread)
    #pragma unroll
    for (int pss = 0; pss < 2; pss++) {
        int idx = pss * 256 + tid;          // float4 index 0..511
        int rr = idx >> 4;
        int jj = (idx & 15) * 4;
        *reinterpret_cast<float4*>(&hs[rr][jj]) =
            *reinterpret_cast<const float4*>(&g_H[(size_t)(r0 + rr) * HH + jj]);
    }
    __syncthreads();

    const int lane = tid & 31;
    const int w    = tid >> 5;
    const int col4 = lane * 4;

    float acc[4][4] = {};

    #pragma unroll
    for (int j = 0; j < HH; j += 4) {
        float4 w0 = *reinterpret_cast<float4*>(&Ws[j + 0][col4]);
        float4 w1 = *reinterpret_cast<float4*>(&Ws[j + 1][col4]);
        float4 w2 = *reinterpret_cast<float4*>(&Ws[j + 2][col4]);
        float4 w3 = *reinterpret_cast<float4*>(&Ws[j + 3][col4]);
        #pragma unroll
        for (int i = 0; i < 4; i++) {
            float4 hv = *reinterpret_cast<float4*>(&hs[w * 4 + i][j]);
            acc[i][0] = fmaf(hv.x, w0.x, acc[i][0]);
            acc[i][0] = fmaf(hv.y, w1.x, acc[i][0]);
            acc[i][0] = fmaf(hv.z, w2.x, acc[i][0]);
            acc[i][0] = fmaf(hv.w, w3.x, acc[i][0]);
            acc[i][1] = fmaf(hv.x, w0.y, acc[i][1]);
            acc[i][1] = fmaf(hv.y, w1.y, acc[i][1]);
            acc[i][1] = fmaf(hv.z, w2.y, acc[i][1]);
            acc[i][1] = fmaf(hv.w, w3.y, acc[i][1]);
            acc[i][2] = fmaf(hv.x, w0.z, acc[i][2]);
            acc[i][2] = fmaf(hv.y, w1.z, acc[i][2]);
            acc[i][2] = fmaf(hv.z, w2.z, acc[i][2]);
            acc[i][2] = fmaf(hv.w, w3.z, acc[i][2]);
            acc[i][3] = fmaf(hv.x, w0.w, acc[i][3]);
            acc[i][3] = fmaf(hv.y, w1.w, acc[i][3]);
            acc[i][3] = fmaf(hv.z, w2.w, acc[i][3]);
            acc[i][3] = fmaf(hv.w, w3.w, acc[i][3]);
        }
    }

    // Bias + softmax per row (row's 128 logits spread 4-per-lane across warp)
    float4 bias4 = *reinterpret_cast<float4*>(&bs[col4]);
    #pragma unroll
    for (int i = 0; i < 4; i++) {
        float l0 = acc[i][0] + bias4.x;
        float l1 = acc[i][1] + bias4.y;
        float l2 = acc[i][2] + bias4.z;
        float l3 = acc[i][3] + bias4.w;

        float mx = fmaxf(fmaxf(l0, l1), fmaxf(l2, l3));
        #pragma unroll
        for (int off = 16; off > 0; off >>= 1)
            mx = fmaxf(mx, __shfl_xor_sync(0xFFFFFFFFu, mx, off));

        float e0 = expf(l0 - mx);
        float e1 = expf(l1 - mx);
        float e2 = expf(l2 - mx);
        float e3 = expf(l3 - mx);
        float s = e0 + e1 + e2 + e3;
        #pragma unroll
        for (int off = 16; off > 0; off >>= 1)
            s += __shfl_xor_sync(0xFFFFFFFFu, s, off);
        float inv = 1.f / s;

        float4 o;
        o.x = e0 * inv; o.y = e1 * inv; o.z = e2 * inv; o.w = e3 * inv;
        size_t row = (size_t)(r0 + w * 4 + i);
        *reinterpret_cast<float4*>(&out[row * VV + col4]) = o;
    }
}

// ---------------------------------------------------------------------------
// Launch
// ---------------------------------------------------------------------------
extern "C" void kernel_launch(void* const* d_in, const int* in_sizes, int n_in,
                              void* d_out, int out_size) {
    const float* x    = (const float*)d_in[0];
    const float* Wf   = (const float*)d_in[1];
    const float* bf   = (const float*)d_in[2];
    const float* Wif  = (const float*)d_in[3];
    const float* bif  = (const float*)d_in[4];
    const float* Wic  = (const float*)d_in[5];
    const float* bic  = (const float*)d_in[6];
    const float* Wo   = (const float*)d_in[7];
    const float* bo   = (const float*)d_in[8];
    const float* Wout = (const float*)d_in[9];
    const float* bout = (const float*)d_in[10];
    float* out = (float*)d_out;

    pack_weights<<<1, 256>>>(Wf, bf, Wif, bif, Wic, bic, Wo, bo);
    gemm_x<<<dim3(MM / 64, GG / 64), 256>>>(x);
    lstm_kernel<<<BB, 256>>>();
    out_proj<<<MM / 32, 256>>>(Wout, bout, out);
}

// round 3
// speedup vs baseline: 1.3288x; 1.3288x over previous
#include <cuda_runtime.h>
#include <cuda_bf16.h>
#include <math.h>

// Problem constants
#define BB   256                 // batch
#define TT   2048                // seq len
#define VV   128                 // vocab / input size
#define HH   64                  // hidden
#define GG   256                 // 4 gates * HH
#define MM   (BB * TT)           // 524288 rows

// Scratch (device-global; no runtime allocation allowed)
__device__ float g_Wx[VV * GG];            // fused x-part weights [128,256]
__device__ float g_Wh[HH * GG];            // fused h-part weights [64,256]
__device__ float g_bias[GG];               // fused gate biases
__device__ float g_preact[(size_t)MM * GG];  // 512 MB: x-part preactivations
__device__ float g_H[(size_t)MM * HH];       // 128 MB: hidden states per step

// Fast transcendentals (MUFU-based, ~1e-6 rel err — safe at 1e-3 tolerance)
__device__ __forceinline__ float fast_sig(float v) {
    return __fdividef(1.f, 1.f + __expf(-v));
}
__device__ __forceinline__ float fast_tanh(float v) {
    return __fdividef(2.f, 1.f + __expf(-2.f * v)) - 1.f;
}
__device__ __forceinline__ unsigned int to_tf32(float v) {
    unsigned int r;
    asm("cvt.rna.tf32.f32 %0, %1;" : "=r"(r) : "f"(v));
    return r;
}

// ---------------------------------------------------------------------------
// Kernel 0: pack 4 gate weight matrices into fused layouts.
// Gate order: 0..63 = f, 64..127 = if, 128..191 = ic(tanh), 192..255 = o
// ---------------------------------------------------------------------------
__global__ void pack_weights(const float* __restrict__ Wf,  const float* __restrict__ bf,
                             const float* __restrict__ Wif, const float* __restrict__ bif,
                             const float* __restrict__ Wic, const float* __restrict__ bic,
                             const float* __restrict__ Wo,  const float* __restrict__ bo) {
    int g = blockIdx.x * blockDim.x + threadIdx.x;
    if (g >= GG) return;
    int gate = g >> 6;
    int col  = g & 63;
    const float* W = (gate == 0) ? Wf : (gate == 1) ? Wif : (gate == 2) ? Wic : Wo;
    const float* bv = (gate == 0) ? bf : (gate == 1) ? bif : (gate == 2) ? bic : bo;
    g_bias[g] = bv[col];
    for (int k = 0; k < VV; k++)
        g_Wx[k * GG + g] = W[k * HH + col];
    for (int j = 0; j < HH; j++)
        g_Wh[j * GG + g] = W[(VV + j) * HH + col];
}

// ---------------------------------------------------------------------------
// Kernel 1: preact[m, g] = x[m, :] @ Wx[:, g] + bias[g]   via TF32 mma.sync
// M=524288, N=256, K=128.  BM=128, BN=64 (grid 4096 x 4), whole K resident.
// 8 warps in 4(M) x 2(N); each warp computes 32x32 with m16n8k8 tiles.
// SMEM: As[128][132] (pad->conflict-free frag loads), Bs[128][72].
// ---------------------------------------------------------------------------
#define AS_STRIDE 132
#define BS_STRIDE 72

__global__ __launch_bounds__(256) void gemm_x(const float* __restrict__ x) {
    extern __shared__ unsigned int smem[];
    unsigned int* As = smem;                       // 128 * 132 words
    unsigned int* Bs = smem + 128 * AS_STRIDE;     // 128 * 72 words

    const int m0 = blockIdx.x * 128;
    const int n0 = blockIdx.y * 64;
    const int tid  = threadIdx.x;
    const int lane = tid & 31;
    const int warp = tid >> 5;
    const int wm = warp >> 1;      // 0..3  (M)
    const int wn = warp & 1;       // 0..1  (N)
    const int gp = lane >> 2;      // 0..7
    const int tq = lane & 3;       // 0..3

    // ---- Load A tile: 128 rows x 128 K (fp32 -> tf32). 16 float4 / thread.
    #pragma unroll
    for (int i = 0; i < 16; i++) {
        int t  = tid + i * 256;            // float4 index 0..4095
        int r  = t >> 5;
        int c4 = (t & 31) * 4;
        float4 v = *reinterpret_cast<const float4*>(&x[(size_t)(m0 + r) * VV + c4]);
        unsigned int* dst = &As[r * AS_STRIDE + c4];
        dst[0] = to_tf32(v.x); dst[1] = to_tf32(v.y);
        dst[2] = to_tf32(v.z); dst[3] = to_tf32(v.w);
    }
    // ---- Load B tile: 128 K x 64 N (fp32 -> tf32). 8 float4 / thread.
    #pragma unroll
    for (int i = 0; i < 8; i++) {
        int t  = tid + i * 256;            // float4 index 0..2047
        int k  = t >> 4;
        int c4 = (t & 15) * 4;
        float4 v = *reinterpret_cast<const float4*>(&g_Wx[(size_t)k * GG + n0 + c4]);
        unsigned int* dst = &Bs[k * BS_STRIDE + c4];
        dst[0] = to_tf32(v.x); dst[1] = to_tf32(v.y);
        dst[2] = to_tf32(v.z); dst[3] = to_tf32(v.w);
    }
    __syncthreads();

    float acc[2][4][4] = {};

    #pragma unroll 4
    for (int ks = 0; ks < 16; ks++) {
        const int k0 = ks * 8;
        // B fragments: 4 n-tiles (reused across both m-tiles)
        unsigned int bf[4][2];
        #pragma unroll
        for (int ni = 0; ni < 4; ni++) {
            int col = wn * 32 + ni * 8 + gp;
            bf[ni][0] = Bs[(k0 + tq)     * BS_STRIDE + col];
            bf[ni][1] = Bs[(k0 + tq + 4) * BS_STRIDE + col];
        }
        #pragma unroll
        for (int mi = 0; mi < 2; mi++) {
            int row = wm * 32 + mi * 16 + gp;
            unsigned int a0 = As[row       * AS_STRIDE + k0 + tq];
            unsigned int a1 = As[(row + 8) * AS_STRIDE + k0 + tq];
            unsigned int a2 = As[row       * AS_STRIDE + k0 + tq + 4];
            unsigned int a3 = As[(row + 8) * AS_STRIDE + k0 + tq + 4];
            #pragma unroll
            for (int ni = 0; ni < 4; ni++) {
                asm volatile(
                    "mma.sync.aligned.m16n8k8.row.col.f32.tf32.tf32.f32 "
                    "{%0,%1,%2,%3}, {%4,%5,%6,%7}, {%8,%9}, {%0,%1,%2,%3};"
                    : "+f"(acc[mi][ni][0]), "+f"(acc[mi][ni][1]),
                      "+f"(acc[mi][ni][2]), "+f"(acc[mi][ni][3])
                    : "r"(a0), "r"(a1), "r"(a2), "r"(a3),
                      "r"(bf[ni][0]), "r"(bf[ni][1]));
            }
        }
    }

    // ---- Epilogue: bias + store (float2 per fragment-row)
    #pragma unroll
    for (int ni = 0; ni < 4; ni++) {
        int bcol = n0 + wn * 32 + ni * 8 + 2 * tq;
        float bv0 = g_bias[bcol];
        float bv1 = g_bias[bcol + 1];
        #pragma unroll
        for (int mi = 0; mi < 2; mi++) {
            int row = m0 + wm * 32 + mi * 16 + gp;
            float2 o0 = make_float2(acc[mi][ni][0] + bv0, acc[mi][ni][1] + bv1);
            float2 o1 = make_float2(acc[mi][ni][2] + bv0, acc[mi][ni][3] + bv1);
            *reinterpret_cast<float2*>(&g_preact[(size_t)row * GG + bcol]) = o0;
            *reinterpret_cast<float2*>(&g_preact[(size_t)(row + 8) * GG + bcol]) = o1;
        }
    }
}

// ---------------------------------------------------------------------------
// Kernel 2: recurrent LSTM. One CTA per batch row, 256 threads (one per gate
// column). W_h lives in registers (64 floats/thread). h broadcast via SMEM,
// c held in registers of threads 0..63. Stores h_t to g_H each step.
// ---------------------------------------------------------------------------
__global__ __launch_bounds__(256, 2) void lstm_kernel() {
    const int b = blockIdx.x;
    const int g = threadIdx.x;

    __shared__ float h_s[HH];
    __shared__ float gates_s[GG];

    // Load this thread's W_h column into registers
    float wh[HH];
    #pragma unroll
    for (int j = 0; j < HH; j++)
        wh[j] = g_Wh[j * GG + g];

    float c = 0.f;
    if (g < HH) h_s[g] = 0.f;
    __syncthreads();

    const float* pa = g_preact + (size_t)b * TT * GG + g;
    float* hout = g_H + (size_t)b * TT * HH;

    float p = pa[0];
    const bool is_tanh_gate = ((g >> 6) == 2);

    for (int t = 0; t < TT; t++) {
        // Prefetch next step's preactivation (hidden behind the FMA loop)
        int tn = (t + 1 < TT) ? (t + 1) : t;
        float pnext = __ldg(&pa[(size_t)tn * GG]);

        // acc = preact + h @ Wh[:, g]
        float acc0 = p, acc1 = 0.f;
        #pragma unroll
        for (int j = 0; j < HH; j += 4) {
            float4 hv = *reinterpret_cast<float4*>(&h_s[j]);
            acc0 = fmaf(hv.x, wh[j + 0], acc0);
            acc1 = fmaf(hv.y, wh[j + 1], acc1);
            acc0 = fmaf(hv.z, wh[j + 2], acc0);
            acc1 = fmaf(hv.w, wh[j + 3], acc1);
        }
        float v = acc0 + acc1;

        // Gate nonlinearity: groups 0,1,3 sigmoid; group 2 tanh (MUFU-based)
        float val = is_tanh_gate ? fast_tanh(v) : fast_sig(v);
        gates_s[g] = val;
        __syncthreads();

        if (g < HH) {
            float f   = gates_s[g];
            float af  = gates_s[HH + g];
            float add = gates_s[2 * HH + g];
            float o   = gates_s[3 * HH + g];
            c = fmaf(c, f, add * af);
            float hn = fast_tanh(c) * o;
            h_s[g] = hn;
            hout[(size_t)t * HH + g] = hn;
        }
        __syncthreads();

        p = pnext;
    }
}

// ---------------------------------------------------------------------------
// Kernel 3: out[m, :] = softmax(h[m, :] @ W_out + b_out)
// 256 threads/block = 8 warps; block tile = 32 rows; each warp 4 rows;
// each lane 4 output columns.  W_out (32 KB) + h tile (8 KB) in SMEM.
// ---------------------------------------------------------------------------
__global__ __launch_bounds__(256) void out_proj(const float* __restrict__ Wout,
                                                const float* __restrict__ bout,
                                                float* __restrict__ out) {
    __shared__ float Ws[HH][VV];       // 32 KB
    __shared__ float hs[32][HH];       // 8 KB
    __shared__ float bs[VV];

    const int r0  = blockIdx.x * 32;
    const int tid = threadIdx.x;

    // Load W_out (64x128 = 2048 float4s, 8 per thread)
    #pragma unroll
    for (int pss = 0; pss < 8; pss++) {
        int idx = pss * 256 + tid;          // float4 index 0..2047
        int rr = idx >> 5;
        int cc = (idx & 31) * 4;
        *reinterpret_cast<float4*>(&Ws[rr][cc]) =
            *reinterpret_cast<const float4*>(&Wout[rr * VV + cc]);
    }
    if (tid < VV) bs[tid] = bout[tid];

    // Load h tile (32 rows x 64 = 512 float4s, 2 per thread)
    #pragma unroll
    for (int pss = 0; pss < 2; pss++) {
        int idx = pss * 256 + tid;          // float4 index 0..511
        int rr = idx >> 4;
        int jj = (idx & 15) * 4;
        *reinterpret_cast<float4*>(&hs[rr][jj]) =
            *reinterpret_cast<const float4*>(&g_H[(size_t)(r0 + rr) * HH + jj]);
    }
    __syncthreads();

    const int lane = tid & 31;
    const int w    = tid >> 5;
    const int col4 = lane * 4;

    float acc[4][4] = {};

    #pragma unroll
    for (int j = 0; j < HH; j += 4) {
        float4 w0 = *reinterpret_cast<float4*>(&Ws[j + 0][col4]);
        float4 w1 = *reinterpret_cast<float4*>(&Ws[j + 1][col4]);
        float4 w2 = *reinterpret_cast<float4*>(&Ws[j + 2][col4]);
        float4 w3 = *reinterpret_cast<float4*>(&Ws[j + 3][col4]);
        #pragma unroll
        for (int i = 0; i < 4; i++) {
            float4 hv = *reinterpret_cast<float4*>(&hs[w * 4 + i][j]);
            acc[i][0] = fmaf(hv.x, w0.x, acc[i][0]);
            acc[i][0] = fmaf(hv.y, w1.x, acc[i][0]);
            acc[i][0] = fmaf(hv.z, w2.x, acc[i][0]);
            acc[i][0] = fmaf(hv.w, w3.x, acc[i][0]);
            acc[i][1] = fmaf(hv.x, w0.y, acc[i][1]);
            acc[i][1] = fmaf(hv.y, w1.y, acc[i][1]);
            acc[i][1] = fmaf(hv.z, w2.y, acc[i][1]);
            acc[i][1] = fmaf(hv.w, w3.y, acc[i][1]);
            acc[i][2] = fmaf(hv.x, w0.z, acc[i][2]);
            acc[i][2] = fmaf(hv.y, w1.z, acc[i][2]);
            acc[i][2] = fmaf(hv.z, w2.z, acc[i][2]);
            acc[i][2] = fmaf(hv.w, w3.z, acc[i][2]);
            acc[i][3] = fmaf(hv.x, w0.w, acc[i][3]);
            acc[i][3] = fmaf(hv.y, w1.w, acc[i][3]);
            acc[i][3] = fmaf(hv.z, w2.w, acc[i][3]);
            acc[i][3] = fmaf(hv.w, w3.w, acc[i][3]);
        }
    }

    // Bias + softmax per row (row's 128 logits spread 4-per-lane across warp)
    float4 bias4 = *reinterpret_cast<float4*>(&bs[col4]);
    #pragma unroll
    for (int i = 0; i < 4; i++) {
        float l0 = acc[i][0] + bias4.x;
        float l1 = acc[i][1] + bias4.y;
        float l2 = acc[i][2] + bias4.z;
        float l3 = acc[i][3] + bias4.w;

        float mx = fmaxf(fmaxf(l0, l1), fmaxf(l2, l3));
        #pragma unroll
        for (int off = 16; off > 0; off >>= 1)
            mx = fmaxf(mx, __shfl_xor_sync(0xFFFFFFFFu, mx, off));

        float e0 = __expf(l0 - mx);
        float e1 = __expf(l1 - mx);
        float e2 = __expf(l2 - mx);
        float e3 = __expf(l3 - mx);
        float s = e0 + e1 + e2 + e3;
        #pragma unroll
        for (int off = 16; off > 0; off >>= 1)
            s += __shfl_xor_sync(0xFFFFFFFFu, s, off);
        float inv = __fdividef(1.f, s);

        float4 o;
        o.x = e0 * inv; o.y = e1 * inv; o.z = e2 * inv; o.w = e3 * inv;
        size_t row = (size_t)(r0 + w * 4 + i);
        *reinterpret_cast<float4*>(&out[row * VV + col4]) = o;
    }
}

// ---------------------------------------------------------------------------
// Launch
// ---------------------------------------------------------------------------
extern "C" void kernel_launch(void* const* d_in, const int* in_sizes, int n_in,
                              void* d_out, int out_size) {
    const float* x    = (const float*)d_in[0];
    const float* Wf   = (const float*)d_in[1];
    const float* bf   = (const float*)d_in[2];
    const float* Wif  = (const float*)d_in[3];
    const float* bif  = (const float*)d_in[4];
    const float* Wic  = (const float*)d_in[5];
    const float* bic  = (const float*)d_in[6];
    const float* Wo   = (const float*)d_in[7];
    const float* bo   = (const float*)d_in[8];
    const float* Wout = (const float*)d_in[9];
    const float* bout = (const float*)d_in[10];
    float* out = (float*)d_out;

    const int gemm_smem = (128 * AS_STRIDE + 128 * BS_STRIDE) * 4;  // 104448 B
    cudaFuncSetAttribute(gemm_x, cudaFuncAttributeMaxDynamicSharedMemorySize,
                         gemm_smem);

    pack_weights<<<1, 256>>>(Wf, bf, Wif, bif, Wic, bic, Wo, bo);
    gemm_x<<<dim3(MM / 128, GG / 64), 256, gemm_smem>>>(x);
    lstm_kernel<<<BB, 256>>>();
    out_proj<<<MM / 32, 256>>>(Wout, bout, out);
}

// round 6
// speedup vs baseline: 1.5138x; 1.1392x over previous
#include <cuda_runtime.h>
#include <cuda_bf16.h>
#include <math.h>

// Problem constants
#define BB   256                 // batch
#define TT   2048                // seq len
#define VV   128                 // vocab / input size
#define HH   64                  // hidden
#define GG   256                 // 4 gates * HH
#define MM   (BB * TT)           // 524288 rows

// Scratch (device-global; no runtime allocation allowed)
__device__ float g_Wx[VV * GG];            // fused x-part weights [128,256]
__device__ float g_Wh[HH * GG];            // fused h-part weights [64,256]
__device__ float g_bias[GG];               // fused gate biases
__device__ float g_preact[(size_t)MM * GG];  // 512 MB: x-part preactivations
__device__ float g_H[(size_t)MM * HH];       // 128 MB: hidden states per step

__device__ __forceinline__ unsigned int to_tf32(float v) {
    unsigned int r;
    asm("cvt.rna.tf32.f32 %0, %1;" : "=r"(r) : "f"(v));
    return r;
}
__device__ __forceinline__ float tanh_fast(float x) {
    float y;
    asm("tanh.approx.f32 %0, %1;" : "=f"(y) : "f"(x));
    return y;
}

// ---------------------------------------------------------------------------
// Kernel 0: pack 4 gate weight matrices into fused layouts.
// Gate order: 0..63 = f, 64..127 = if, 128..191 = ic(tanh), 192..255 = o
// ---------------------------------------------------------------------------
__global__ void pack_weights(const float* __restrict__ Wf,  const float* __restrict__ bf,
                             const float* __restrict__ Wif, const float* __restrict__ bif,
                             const float* __restrict__ Wic, const float* __restrict__ bic,
                             const float* __restrict__ Wo,  const float* __restrict__ bo) {
    int g = blockIdx.x * blockDim.x + threadIdx.x;
    if (g >= GG) return;
    int gate = g >> 6;
    int col  = g & 63;
    const float* W = (gate == 0) ? Wf : (gate == 1) ? Wif : (gate == 2) ? Wic : Wo;
    const float* bv = (gate == 0) ? bf : (gate == 1) ? bif : (gate == 2) ? bic : bo;
    g_bias[g] = bv[col];
    for (int k = 0; k < VV; k++)
        g_Wx[k * GG + g] = W[k * HH + col];
    for (int j = 0; j < HH; j++)
        g_Wh[j * GG + g] = W[(VV + j) * HH + col];
}

// ---------------------------------------------------------------------------
// Kernel 1: preact[m, g] = x[m, :] @ Wx[:, g] + bias[g]   via TF32 mma.sync
// M=524288, N=256, K=128.  BM=128, whole K resident; CTA loops over all 4
// n-blocks of 64 reusing the A tile (x read from DRAM exactly once).
// 8 warps in 4(M) x 2(N); each warp computes 32x32 with m16n8k8 tiles.
// ---------------------------------------------------------------------------
#define AS_STRIDE 132
#define BS_STRIDE 72

__global__ __launch_bounds__(256) void gemm_x(const float* __restrict__ x) {
    extern __shared__ unsigned int smem[];
    unsigned int* As = smem;                       // 128 * 132 words
    unsigned int* Bs = smem + 128 * AS_STRIDE;     // 128 * 72 words

    const int m0 = blockIdx.x * 128;
    const int tid  = threadIdx.x;
    const int lane = tid & 31;
    const int warp = tid >> 5;
    const int wm = warp >> 1;      // 0..3  (M)
    const int wn = warp & 1;       // 0..1  (N)
    const int gp = lane >> 2;      // 0..7
    const int tq = lane & 3;       // 0..3

    // ---- Load A tile: 128 rows x 128 K (fp32 -> tf32). 16 float4 / thread.
    #pragma unroll
    for (int i = 0; i < 16; i++) {
        int t  = tid + i * 256;            // float4 index 0..4095
        int r  = t >> 5;
        int c4 = (t & 31) * 4;
        float4 v = *reinterpret_cast<const float4*>(&x[(size_t)(m0 + r) * VV + c4]);
        unsigned int* dst = &As[r * AS_STRIDE + c4];
        dst[0] = to_tf32(v.x); dst[1] = to_tf32(v.y);
        dst[2] = to_tf32(v.z); dst[3] = to_tf32(v.w);
    }

    for (int nb = 0; nb < 4; nb++) {
        const int n0 = nb * 64;
        __syncthreads();   // A ready (first iter) / prev mma done with Bs

        // ---- Load B tile: 128 K x 64 N (fp32 -> tf32). 8 float4 / thread.
        #pragma unroll
        for (int i = 0; i < 8; i++) {
            int t  = tid + i * 256;            // float4 index 0..2047
            int k  = t >> 4;
            int c4 = (t & 15) * 4;
            float4 v = *reinterpret_cast<const float4*>(&g_Wx[(size_t)k * GG + n0 + c4]);
            unsigned int* dst = &Bs[k * BS_STRIDE + c4];
            dst[0] = to_tf32(v.x); dst[1] = to_tf32(v.y);
            dst[2] = to_tf32(v.z); dst[3] = to_tf32(v.w);
        }
        __syncthreads();

        float acc[2][4][4] = {};

        #pragma unroll 4
        for (int ks = 0; ks < 16; ks++) {
            const int k0 = ks * 8;
            unsigned int bfr[4][2];
            #pragma unroll
            for (int ni = 0; ni < 4; ni++) {
                int col = wn * 32 + ni * 8 + gp;
                bfr[ni][0] = Bs[(k0 + tq)     * BS_STRIDE + col];
                bfr[ni][1] = Bs[(k0 + tq + 4) * BS_STRIDE + col];
            }
            #pragma unroll
            for (int mi = 0; mi < 2; mi++) {
                int row = wm * 32 + mi * 16 + gp;
                unsigned int a0 = As[row       * AS_STRIDE + k0 + tq];
                unsigned int a1 = As[(row + 8) * AS_STRIDE + k0 + tq];
                unsigned int a2 = As[row       * AS_STRIDE + k0 + tq + 4];
                unsigned int a3 = As[(row + 8) * AS_STRIDE + k0 + tq + 4];
                #pragma unroll
                for (int ni = 0; ni < 4; ni++) {
                    asm volatile(
                        "mma.sync.aligned.m16n8k8.row.col.f32.tf32.tf32.f32 "
                        "{%0,%1,%2,%3}, {%4,%5,%6,%7}, {%8,%9}, {%0,%1,%2,%3};"
                        : "+f"(acc[mi][ni][0]), "+f"(acc[mi][ni][1]),
                          "+f"(acc[mi][ni][2]), "+f"(acc[mi][ni][3])
                        : "r"(a0), "r"(a1), "r"(a2), "r"(a3),
                          "r"(bfr[ni][0]), "r"(bfr[ni][1]));
                }
            }
        }

        // ---- Epilogue: bias + store (float2 per fragment-row)
        #pragma unroll
        for (int ni = 0; ni < 4; ni++) {
            int bcol = n0 + wn * 32 + ni * 8 + 2 * tq;
            float bv0 = g_bias[bcol];
            float bv1 = g_bias[bcol + 1];
            #pragma unroll
            for (int mi = 0; mi < 2; mi++) {
                int row = m0 + wm * 32 + mi * 16 + gp;
                float2 o0 = make_float2(acc[mi][ni][0] + bv0, acc[mi][ni][1] + bv1);
                float2 o1 = make_float2(acc[mi][ni][2] + bv0, acc[mi][ni][3] + bv1);
                *reinterpret_cast<float2*>(&g_preact[(size_t)row * GG + bcol]) = o0;
                *reinterpret_cast<float2*>(&g_preact[(size_t)(row + 8) * GG + bcol]) = o1;
            }
        }
    }
}

// ---------------------------------------------------------------------------
// Kernel 2: recurrent LSTM. One CTA per batch row, 256 threads (one per gate
// column). W_h in registers; h broadcast via SMEM; c in threads 0..63.
// 4-deep preact prefetch FIFO hides DRAM latency; tanh.approx nonlinearities.
// ---------------------------------------------------------------------------
__global__ __launch_bounds__(256, 2) void lstm_kernel() {
    const int b = blockIdx.x;
    const int g = threadIdx.x;

    __shared__ float h_s[HH];
    __shared__ float gates_s[GG];

    // Load this thread's W_h column into registers
    float wh[HH];
    #pragma unroll
    for (int j = 0; j < HH; j++)
        wh[j] = g_Wh[j * GG + g];

    float c = 0.f;
    if (g < HH) h_s[g] = 0.f;
    __syncthreads();

    const float* pa = g_preact + (size_t)b * TT * GG + g;
    float* hout = g_H + (size_t)b * TT * HH;

    // sigmoid(v) = 0.5*tanh(0.5v)+0.5 ; tanh gate uses (1,1,0)
    const bool is_tanh_gate = ((g >> 6) == 2);
    const float pre    = is_tanh_gate ? 1.f : 0.5f;
    const float post_m = is_tanh_gate ? 1.f : 0.5f;
    const float post_b = is_tanh_gate ? 0.f : 0.5f;

    // 4-deep prefetch FIFO
    float f0 = __ldg(pa + 0 * GG);
    float f1 = __ldg(pa + 1 * GG);
    float f2 = __ldg(pa + 2 * GG);
    float f3 = __ldg(pa + 3 * GG);

    for (int t = 0; t < TT; t++) {
        float p = f0;
        f0 = f1; f1 = f2; f2 = f3;
        int tn = (t + 4 < TT) ? (t + 4) : (TT - 1);
        f3 = __ldg(pa + (size_t)tn * GG);

        // acc = preact + h @ Wh[:, g]   (4 accumulators, chain depth 8)
        float a0 = p, a1 = 0.f, a2 = 0.f, a3 = 0.f;
        #pragma unroll
        for (int j = 0; j < HH; j += 4) {
            float4 hv = *reinterpret_cast<float4*>(&h_s[j]);
            a0 = fmaf(hv.x, wh[j + 0], a0);
            a1 = fmaf(hv.y, wh[j + 1], a1);
            a2 = fmaf(hv.z, wh[j + 2], a2);
            a3 = fmaf(hv.w, wh[j + 3], a3);
        }
        float v = (a0 + a1) + (a2 + a3);

        gates_s[g] = fmaf(tanh_fast(v * pre), post_m, post_b);
        __syncthreads();

        if (g < HH) {
            float f   = gates_s[g];
            float af  = gates_s[HH + g];
            float add = gates_s[2 * HH + g];
            float o   = gates_s[3 * HH + g];
            c = fmaf(c, f, add * af);
            float hn = tanh_fast(c) * o;
            h_s[g] = hn;
            hout[(size_t)t * HH + g] = hn;
        }
        __syncthreads();
    }
}

// ---------------------------------------------------------------------------
// Kernel 3: out[m, :] = softmax(h[m, :] @ W_out + b_out)  via TF32 mma
// CTA = 128 rows, 256 threads / 8 warps; warp = 16 rows x full N=128, K=64.
// Softmax on fragments: row's 128 logits live in 4 lanes (quad shfl reduce).
// ---------------------------------------------------------------------------
#define HS_STRIDE 68
#define WS_STRIDE 136

__global__ __launch_bounds__(256, 2) void out_proj(const float* __restrict__ Wout,
                                                   const float* __restrict__ bout,
                                                   float* __restrict__ out) {
    extern __shared__ unsigned int sm[];
    unsigned int* Hs = sm;                                 // 128 * 68 words
    unsigned int* Ws = sm + 128 * HS_STRIDE;               // 64 * 136 words
    float* bs = (float*)(sm + 128 * HS_STRIDE + 64 * WS_STRIDE);  // 128 floats

    const int r0   = blockIdx.x * 128;
    const int tid  = threadIdx.x;
    const int lane = tid & 31;
    const int warp = tid >> 5;
    const int gp = lane >> 2;      // 0..7
    const int tq = lane & 3;       // 0..3

    // Load h tile: 128 rows x 64 (fp32 -> tf32). 8 float4 / thread.
    #pragma unroll
    for (int i = 0; i < 8; i++) {
        int t  = tid + i * 256;        // 0..2047
        int r  = t >> 4;
        int c4 = (t & 15) * 4;
        float4 v = *reinterpret_cast<const float4*>(&g_H[(size_t)(r0 + r) * HH + c4]);
        unsigned int* d = &Hs[r * HS_STRIDE + c4];
        d[0] = to_tf32(v.x); d[1] = to_tf32(v.y);
        d[2] = to_tf32(v.z); d[3] = to_tf32(v.w);
    }
    // Load W_out [64 K x 128 N]. 8 float4 / thread.
    #pragma unroll
    for (int i = 0; i < 8; i++) {
        int t  = tid + i * 256;
        int k  = t >> 5;
        int c4 = (t & 31) * 4;
        float4 v = *reinterpret_cast<const float4*>(&Wout[k * VV + c4]);
        unsigned int* d = &Ws[k * WS_STRIDE + c4];
        d[0] = to_tf32(v.x); d[1] = to_tf32(v.y);
        d[2] = to_tf32(v.z); d[3] = to_tf32(v.w);
    }
    if (tid < VV) bs[tid] = bout[tid];
    __syncthreads();

    float acc[16][4] = {};
    const int rowA = warp * 16 + gp;

    #pragma unroll
    for (int ks = 0; ks < 8; ks++) {
        const int k0 = ks * 8;
        unsigned int a0 = Hs[rowA       * HS_STRIDE + k0 + tq];
        unsigned int a1 = Hs[(rowA + 8) * HS_STRIDE + k0 + tq];
        unsigned int a2 = Hs[rowA       * HS_STRIDE + k0 + tq + 4];
        unsigned int a3 = Hs[(rowA + 8) * HS_STRIDE + k0 + tq + 4];
        #pragma unroll
        for (int ni = 0; ni < 16; ni++) {
            unsigned int b0 = Ws[(k0 + tq)     * WS_STRIDE + ni * 8 + gp];
            unsigned int b1 = Ws[(k0 + tq + 4) * WS_STRIDE + ni * 8 + gp];
            asm volatile(
                "mma.sync.aligned.m16n8k8.row.col.f32.tf32.tf32.f32 "
                "{%0,%1,%2,%3}, {%4,%5,%6,%7}, {%8,%9}, {%0,%1,%2,%3};"
                : "+f"(acc[ni][0]), "+f"(acc[ni][1]),
                  "+f"(acc[ni][2]), "+f"(acc[ni][3])
                : "r"(a0), "r"(a1), "r"(a2), "r"(a3), "r"(b0), "r"(b1));
        }
    }

    // Softmax: thread holds rows (rowA, rowA+8); row's logits in 4 lanes (tq).
    #pragma unroll
    for (int rr = 0; rr < 2; rr++) {
        float l[32];
        #pragma unroll
        for (int ni = 0; ni < 16; ni++) {
            float b0 = bs[ni * 8 + 2 * tq];
            float b1 = bs[ni * 8 + 2 * tq + 1];
            l[2 * ni]     = acc[ni][2 * rr]     + b0;
            l[2 * ni + 1] = acc[ni][2 * rr + 1] + b1;
        }
        float mx = l[0];
        #pragma unroll
        for (int i = 1; i < 32; i++) mx = fmaxf(mx, l[i]);
        mx = fmaxf(mx, __shfl_xor_sync(0xFFFFFFFFu, mx, 1));
        mx = fmaxf(mx, __shfl_xor_sync(0xFFFFFFFFu, mx, 2));

        float s = 0.f;
        #pragma unroll
        for (int i = 0; i < 32; i++) { l[i] = __expf(l[i] - mx); s += l[i]; }
        s += __shfl_xor_sync(0xFFFFFFFFu, s, 1);
        s += __shfl_xor_sync(0xFFFFFFFFu, s, 2);
        float inv = __fdividef(1.f, s);

        size_t row = (size_t)(r0 + rowA + rr * 8);
        #pragma unroll
        for (int ni = 0; ni < 16; ni++) {
            float2 o = make_float2(l[2 * ni] * inv, l[2 * ni + 1] * inv);
            *reinterpret_cast<float2*>(&out[row * VV + ni * 8 + 2 * tq]) = o;
        }
    }
}

// ---------------------------------------------------------------------------
// Launch
// ---------------------------------------------------------------------------
extern "C" void kernel_launch(void* const* d_in, const int* in_sizes, int n_in,
                              void* d_out, int out_size) {
    const float* x    = (const float*)d_in[0];
    const float* Wf   = (const float*)d_in[1];
    const float* bf   = (const float*)d_in[2];
    const float* Wif  = (const float*)d_in[3];
    const float* bif  = (const float*)d_in[4];
    const float* Wic  = (const float*)d_in[5];
    const float* bic  = (const float*)d_in[6];
    const float* Wo   = (const float*)d_in[7];
    const float* bo   = (const float*)d_in[8];
    const float* Wout = (const float*)d_in[9];
    const float* bout = (const float*)d_in[10];
    float* out = (float*)d_out;

    const int gemm_smem = (128 * AS_STRIDE + 128 * BS_STRIDE) * 4;         // 104448 B
    const int proj_smem = (128 * HS_STRIDE + 64 * WS_STRIDE + 128) * 4;    // 70144 B
    cudaFuncSetAttribute(gemm_x, cudaFuncAttributeMaxDynamicSharedMemorySize,
                         gemm_smem);
    cudaFuncSetAttribute(out_proj, cudaFuncAttributeMaxDynamicSharedMemorySize,
                         proj_smem);

    pack_weights<<<1, 256>>>(Wf, bf, Wif, bif, Wic, bic, Wo, bo);
    gemm_x<<<MM / 128, 256, gemm_smem>>>(x);
    lstm_kernel<<<BB, 256>>>();
    out_proj<<<MM / 128, 256, proj_smem>>>(Wout, bout, out);
}